// round 15
// baseline (speedup 1.0000x reference)
#include <cuda_runtime.h>
#include <cuda_fp16.h>
#include <cstdint>

#define BB   16
#define CC   128
#define HH   28
#define WW   28
#define FF   128
#define KK   1152      // CC*9
#define LL   784       // 28*28
#define BL   (BB * LL) // 12544 = 196*64 exactly
#define NLT  196       // l-tiles of 64 over flat (b,l)
#define FT   64
#define LT   64
#define KC   32
#define NKC  (KK/KC)   // 36
#define KSPL 4
#define STG_PER (NKC / KSPL)   // 9

// Scratch (allocation-free rule: __device__ globals). Values prescaled by 0.25.
__device__ __align__(16) __half g_Pneg[(size_t)KK * BL];              // -0.25*patches (fp16), [K][B*L] flat
__device__ __align__(16) __half g_Wd [(size_t)KK * 2 * FF];           // 0.25*W transposed+duplicated [K][2F]
__device__ __align__(16) __half g_part[(size_t)KSPL * FF * BL];       // k-split partials (fp16), [ks][F][B*L]

#define P_BLOCKS 2048      // one block per (b,c) plane
#define W_BLOCKS 576       // 128*1152 / 256

// ---------------- prep: plane-staged im2col (no bounds checks) + W transpose/dup ----------------
__global__ void __launch_bounds__(256) prep_kernel(const float* __restrict__ x,
                                                   const float* __restrict__ Wg) {
    int bid = blockIdx.x;
    if (bid >= P_BLOCKS) {
        // W transpose + duplicate + prescale
        int gid = (bid - P_BLOCKS) * 256 + threadIdx.x;    // < 147456
        int k = gid % KK, f = gid / KK;
        __half h = __float2half_rn(0.25f * Wg[f * KK + k]);
        __half2 d = __halves2half2(h, h);
        *reinterpret_cast<uint32_t*>(&g_Wd[(size_t)k * (2 * FF) + 2 * f]) =
            *reinterpret_cast<uint32_t*>(&d);
        return;
    }
    // zero-padded plane: rows 0..29 (= ih+1), cols 0..29 of 33 (= iw+1); 33 stride kills bank conflicts
    __shared__ float sp[30][33];
    const int tid = threadIdx.x;
    const int b = bid >> 7;
    const int c = bid & 127;

    for (int i = tid; i < 30 * 33; i += 256) (&sp[0][0])[i] = 0.f;
    __syncthreads();

    const int oh = tid / 7;               // valid for tid<196
    const int ow = (tid - oh * 7) * 4;

    if (tid < 196) {
        const float4 v = reinterpret_cast<const float4*>(
            x + ((size_t)(b * CC + c)) * (HH * WW))[tid];
        // negate + prescale on the way in; pad stays exactly 0
        sp[oh + 1][ow + 1] = -0.25f * v.x;
        sp[oh + 1][ow + 2] = -0.25f * v.y;
        sp[oh + 1][ow + 3] = -0.25f * v.z;
        sp[oh + 1][ow + 4] = -0.25f * v.w;
    }
    __syncthreads();

    if (tid < 196) {
        __half* dst = g_Pneg + (size_t)(c * 9) * BL + b * LL + tid * 4;
#pragma unroll
        for (int kh = 0; kh < 3; kh++)
#pragma unroll
            for (int kw = 0; kw < 3; kw++) {
                const float* rr = &sp[oh + kh][ow + kw];
                __half2 h0 = __floats2half2_rn(rr[0], rr[1]);
                __half2 h1 = __floats2half2_rn(rr[2], rr[3]);
                uint2 st;
                st.x = *reinterpret_cast<uint32_t*>(&h0);
                st.y = *reinterpret_cast<uint32_t*>(&h1);
                *reinterpret_cast<uint2*>(&dst[(size_t)(kh * 3 + kw) * BL]) = st;
            }
    }
}

#define CPA16(s, g) asm volatile("cp.async.cg.shared.global [%0], [%1], 16;\n" :: "r"(s), "l"(g))

// ---------------- main L1-distance kernel (fp16, dup-W, habs2, k-split x4, flat-BL) ----------------
// grid (196, 8): y = fhalf + 2*ksplit. 1568 CTAs, 9 stages each.
__global__ void __launch_bounds__(256) adder_kernel() {
    __shared__ __align__(16) __half2 sWd[2][KC][FT];      // 16 KB
    __shared__ __align__(16) __half2 sP [2][KC][LT / 2];  // 8 KB

    const int tid = threadIdx.x;
    const int fh  = blockIdx.y & 1;
    const int ks  = blockIdx.y >> 1;
    const int f0  = fh * FT;
    const int l0  = blockIdx.x * LT;         // flat (b,l) offset
    const int s0  = ks * STG_PER;

    const __half* gW = g_Wd + 2 * f0;        // [K][2F] slice
    const __half* gP = g_Pneg + l0;          // [K][BL] slice

    const uint32_t sW_base = (uint32_t)__cvta_generic_to_shared(&sWd[0][0][0]);
    const uint32_t sP_base = (uint32_t)__cvta_generic_to_shared(&sP[0][0][0]);

    const int frow = tid >> 3;            // 0..31
    const int fch  = (tid & 7);           // 0..7

    auto fill = [&](int s, int bufi) {
        int k0 = s * KC;
        const __half* wr = gW + (size_t)(k0 + frow) * (2 * FF);
        uint32_t wd = sW_base + (uint32_t)((bufi * KC + frow) * (FT * 4));
        CPA16(wd + (2 * fch) * 16,     wr + (2 * fch) * 8);
        CPA16(wd + (2 * fch + 1) * 16, wr + (2 * fch + 1) * 8);
        const __half* pr = gP + (size_t)(k0 + frow) * BL;
        uint32_t pd = sP_base + (uint32_t)((bufi * KC + frow) * (LT * 2));
        CPA16(pd + fch * 16, pr + fch * 8);
        asm volatile("cp.async.commit_group;\n" ::: "memory");
    };

    const int tc  = tid & 15;             // f = 4tc .. 4tc+3
    const int tl2 = (tid >> 4) * 2;       // half2 idx: l = 4*(tid>>4) ..+3

    __half2 hacc[4][2];                   // [fi][lpair], fp16 partial (<=2 stages = 64 k)
    float accf[4][4];                     // [fi][l], fp32 running
#pragma unroll
    for (int i = 0; i < 4; i++) {
        hacc[i][0] = __float2half2_rn(0.f);
        hacc[i][1] = __float2half2_rn(0.f);
#pragma unroll
        for (int j = 0; j < 4; j++) accf[i][j] = 0.f;
    }

    fill(s0, 0);
    for (int t = 0; t < STG_PER; t++) {
        asm volatile("cp.async.wait_group 0;\n" ::: "memory");
        __syncthreads();
        if (t + 1 < STG_PER) fill(s0 + t + 1, (t + 1) & 1);
        const int buf = t & 1;
#pragma unroll
        for (int kc = 0; kc < KC; kc++) {
            uint4 wu = *reinterpret_cast<const uint4*>(&sWd[buf][kc][4 * tc]); // 4 dup half2
            uint2 pu = *reinterpret_cast<const uint2*>(&sP[buf][kc][tl2]);     // (p0,p1),(p2,p3)
            __half2 p01 = *reinterpret_cast<__half2*>(&pu.x);
            __half2 p23 = *reinterpret_cast<__half2*>(&pu.y);
            __half2 w[4];
            w[0] = *reinterpret_cast<__half2*>(&wu.x);
            w[1] = *reinterpret_cast<__half2*>(&wu.y);
            w[2] = *reinterpret_cast<__half2*>(&wu.z);
            w[3] = *reinterpret_cast<__half2*>(&wu.w);
#pragma unroll
            for (int i = 0; i < 4; i++) {
                __half2 d0 = __hadd2(w[i], p01);   // w - p (p negated)
                __half2 d1 = __hadd2(w[i], p23);
                hacc[i][0] = __hadd2(hacc[i][0], __habs2(d0));   // |.| folds into HADD2 src-mod
                hacc[i][1] = __hadd2(hacc[i][1], __habs2(d1));
            }
        }
        // flush fp16 partials to fp32 every 2 stages (and at the end)
        if ((t & 1) == 1 || t == STG_PER - 1) {
#pragma unroll
            for (int i = 0; i < 4; i++) {
#pragma unroll
                for (int j = 0; j < 2; j++) {
                    float2 tt = __half22float2(hacc[i][j]);
                    accf[i][2 * j]     += tt.x;
                    accf[i][2 * j + 1] += tt.y;
                    hacc[i][j] = __float2half2_rn(0.f);
                }
            }
        }
    }

    // store fp16 partial sums [ks][F][BL]
    const int lflat = l0 + (tid >> 4) * 4;
    __half* pout = g_part + (size_t)ks * (FF * BL);
#pragma unroll
    for (int i = 0; i < 4; i++) {
        __half2 h0 = __floats2half2_rn(accf[i][0], accf[i][1]);
        __half2 h1 = __floats2half2_rn(accf[i][2], accf[i][3]);
        uint2 st;
        st.x = *reinterpret_cast<uint32_t*>(&h0);
        st.y = *reinterpret_cast<uint32_t*>(&h1);
        int f = f0 + 4 * tc + i;
        *reinterpret_cast<uint2*>(&pout[(size_t)f * BL + lflat]) = st;
    }
}

// ---------------- reduce: out[b][f][l] = -4 * sum_ks part[ks][f][b*784+l] ----------------
__global__ void __launch_bounds__(256) reduce_kernel(float* __restrict__ out) {
    int i = blockIdx.x * 256 + threadIdx.x;     // out float4 index, < 401408
    int o = i * 4;
    int b = o / (FF * LL);
    int rem = o - b * (FF * LL);
    int f = rem / LL;
    int l = rem - f * LL;
    size_t p = (size_t)f * BL + b * LL + l;     // halves, 4-aligned

    float s[4] = {0.f, 0.f, 0.f, 0.f};
#pragma unroll
    for (int ks = 0; ks < KSPL; ks++) {
        uint2 u = *reinterpret_cast<const uint2*>(&g_part[(size_t)ks * (FF * BL) + p]);
        __half2 h0 = *reinterpret_cast<__half2*>(&u.x);
        __half2 h1 = *reinterpret_cast<__half2*>(&u.y);
        float2 a = __half22float2(h0);
        float2 c = __half22float2(h1);
        s[0] += a.x; s[1] += a.y; s[2] += c.x; s[3] += c.y;
    }
    float4 v = make_float4(-4.f * s[0], -4.f * s[1], -4.f * s[2], -4.f * s[3]);
    reinterpret_cast<float4*>(out)[i] = v;
}

extern "C" void kernel_launch(void* const* d_in, const int* in_sizes, int n_in,
                              void* d_out, int out_size) {
    const float* x  = (const float*)d_in[0];   // [16,128,28,28]
    const float* Wg = (const float*)d_in[1];   // [128,128,3,3]
    float* out = (float*)d_out;                // [16,128,28,28]

    prep_kernel<<<P_BLOCKS + W_BLOCKS, 256>>>(x, Wg);

    dim3 grid(NLT /*196*/, 2 * KSPL /*8*/, 1);
    adder_kernel<<<grid, 256>>>();

    reduce_kernel<<<(BB * FF * LL / 4) / 256 /*1568*/, 256>>>(out);
}

// round 16
// speedup vs baseline: 1.0163x; 1.0163x over previous
#include <cuda_runtime.h>
#include <cuda_fp16.h>
#include <cstdint>

#define BB   16
#define CC   128
#define HH   28
#define WW   28
#define FF   128
#define KK   1152      // CC*9
#define LL   784       // 28*28
#define BL   (BB * LL) // 12544 = 196*64 exactly
#define NLT  196       // l-tiles of 64 over flat (b,l)
#define FT   64
#define LT   64
#define KC   32
#define NKC  (KK/KC)   // 36
#define KSPL 6
#define STG_PER (NKC / KSPL)   // 6

// Scratch (allocation-free rule: __device__ globals). Values prescaled by 0.25.
__device__ __align__(16) __half g_Pneg[(size_t)KK * BL];              // -0.25*patches (fp16), [K][B*L] flat
__device__ __align__(16) __half g_Wd [(size_t)KK * 2 * FF];           // 0.25*W transposed+duplicated [K][2F]
__device__ __align__(16) __half g_part[(size_t)KSPL * FF * BL];       // k-split partials (fp16), [ks][F][B*L]

#define P_BLOCKS 2048      // one block per (b,c) plane
#define W_BLOCKS 576       // 128*1152 / 256

// ---------------- prep: plane-staged im2col (no bounds checks) + W transpose/dup ----------------
__global__ void __launch_bounds__(256) prep_kernel(const float* __restrict__ x,
                                                   const float* __restrict__ Wg) {
    int bid = blockIdx.x;
    if (bid >= P_BLOCKS) {
        // W transpose + duplicate + prescale
        int gid = (bid - P_BLOCKS) * 256 + threadIdx.x;    // < 147456
        int k = gid % KK, f = gid / KK;
        __half h = __float2half_rn(0.25f * Wg[f * KK + k]);
        __half2 d = __halves2half2(h, h);
        *reinterpret_cast<uint32_t*>(&g_Wd[(size_t)k * (2 * FF) + 2 * f]) =
            *reinterpret_cast<uint32_t*>(&d);
        return;
    }
    // zero-padded plane: rows 0..29 (= ih+1), cols 0..29 of 33 (= iw+1); 33 stride kills bank conflicts
    __shared__ float sp[30][33];
    const int tid = threadIdx.x;
    const int b = bid >> 7;
    const int c = bid & 127;

    for (int i = tid; i < 30 * 33; i += 256) (&sp[0][0])[i] = 0.f;
    __syncthreads();

    const int oh = tid / 7;               // valid for tid<196
    const int ow = (tid - oh * 7) * 4;

    if (tid < 196) {
        const float4 v = reinterpret_cast<const float4*>(
            x + ((size_t)(b * CC + c)) * (HH * WW))[tid];
        // negate + prescale on the way in; pad stays exactly 0
        sp[oh + 1][ow + 1] = -0.25f * v.x;
        sp[oh + 1][ow + 2] = -0.25f * v.y;
        sp[oh + 1][ow + 3] = -0.25f * v.z;
        sp[oh + 1][ow + 4] = -0.25f * v.w;
    }
    __syncthreads();

    if (tid < 196) {
        __half* dst = g_Pneg + (size_t)(c * 9) * BL + b * LL + tid * 4;
#pragma unroll
        for (int kh = 0; kh < 3; kh++)
#pragma unroll
            for (int kw = 0; kw < 3; kw++) {
                const float* rr = &sp[oh + kh][ow + kw];
                __half2 h0 = __floats2half2_rn(rr[0], rr[1]);
                __half2 h1 = __floats2half2_rn(rr[2], rr[3]);
                uint2 st;
                st.x = *reinterpret_cast<uint32_t*>(&h0);
                st.y = *reinterpret_cast<uint32_t*>(&h1);
                *reinterpret_cast<uint2*>(&dst[(size_t)(kh * 3 + kw) * BL]) = st;
            }
    }
}

#define CPA16(s, g) asm volatile("cp.async.cg.shared.global [%0], [%1], 16;\n" :: "r"(s), "l"(g))

// ---------------- main L1-distance kernel (fp16, dup-W, habs2, k-split x6, flat-BL) ----------------
// grid (196, 12): y = fhalf + 2*ksplit. 2352 CTAs, 6 stages each (~3.97 residency waves).
__global__ void __launch_bounds__(256) adder_kernel() {
    __shared__ __align__(16) __half2 sWd[2][KC][FT];      // 16 KB
    __shared__ __align__(16) __half2 sP [2][KC][LT / 2];  // 8 KB

    const int tid = threadIdx.x;
    const int fh  = blockIdx.y & 1;
    const int ks  = blockIdx.y >> 1;
    const int f0  = fh * FT;
    const int l0  = blockIdx.x * LT;         // flat (b,l) offset
    const int s0  = ks * STG_PER;

    const __half* gW = g_Wd + 2 * f0;        // [K][2F] slice
    const __half* gP = g_Pneg + l0;          // [K][BL] slice

    const uint32_t sW_base = (uint32_t)__cvta_generic_to_shared(&sWd[0][0][0]);
    const uint32_t sP_base = (uint32_t)__cvta_generic_to_shared(&sP[0][0][0]);

    const int frow = tid >> 3;            // 0..31
    const int fch  = (tid & 7);           // 0..7

    auto fill = [&](int s, int bufi) {
        int k0 = s * KC;
        const __half* wr = gW + (size_t)(k0 + frow) * (2 * FF);
        uint32_t wd = sW_base + (uint32_t)((bufi * KC + frow) * (FT * 4));
        CPA16(wd + (2 * fch) * 16,     wr + (2 * fch) * 8);
        CPA16(wd + (2 * fch + 1) * 16, wr + (2 * fch + 1) * 8);
        const __half* pr = gP + (size_t)(k0 + frow) * BL;
        uint32_t pd = sP_base + (uint32_t)((bufi * KC + frow) * (LT * 2));
        CPA16(pd + fch * 16, pr + fch * 8);
        asm volatile("cp.async.commit_group;\n" ::: "memory");
    };

    const int tc  = tid & 15;             // f = 4tc .. 4tc+3
    const int tl2 = (tid >> 4) * 2;       // half2 idx: l = 4*(tid>>4) ..+3

    __half2 hacc[4][2];                   // [fi][lpair], fp16 partial (<=2 stages = 64 k)
    float accf[4][4];                     // [fi][l], fp32 running
#pragma unroll
    for (int i = 0; i < 4; i++) {
        hacc[i][0] = __float2half2_rn(0.f);
        hacc[i][1] = __float2half2_rn(0.f);
#pragma unroll
        for (int j = 0; j < 4; j++) accf[i][j] = 0.f;
    }

    fill(s0, 0);
    for (int t = 0; t < STG_PER; t++) {
        asm volatile("cp.async.wait_group 0;\n" ::: "memory");
        __syncthreads();
        if (t + 1 < STG_PER) fill(s0 + t + 1, (t + 1) & 1);
        const int buf = t & 1;
#pragma unroll
        for (int kc = 0; kc < KC; kc++) {
            uint4 wu = *reinterpret_cast<const uint4*>(&sWd[buf][kc][4 * tc]); // 4 dup half2
            uint2 pu = *reinterpret_cast<const uint2*>(&sP[buf][kc][tl2]);     // (p0,p1),(p2,p3)
            __half2 p01 = *reinterpret_cast<__half2*>(&pu.x);
            __half2 p23 = *reinterpret_cast<__half2*>(&pu.y);
            __half2 w[4];
            w[0] = *reinterpret_cast<__half2*>(&wu.x);
            w[1] = *reinterpret_cast<__half2*>(&wu.y);
            w[2] = *reinterpret_cast<__half2*>(&wu.z);
            w[3] = *reinterpret_cast<__half2*>(&wu.w);
#pragma unroll
            for (int i = 0; i < 4; i++) {
                __half2 d0 = __hadd2(w[i], p01);   // w - p (p negated)
                __half2 d1 = __hadd2(w[i], p23);
                hacc[i][0] = __hadd2(hacc[i][0], __habs2(d0));   // |.| folds into HADD2 src-mod
                hacc[i][1] = __hadd2(hacc[i][1], __habs2(d1));
            }
        }
        // flush fp16 partials to fp32 every 2 stages (and at the end)
        if ((t & 1) == 1 || t == STG_PER - 1) {
#pragma unroll
            for (int i = 0; i < 4; i++) {
#pragma unroll
                for (int j = 0; j < 2; j++) {
                    float2 tt = __half22float2(hacc[i][j]);
                    accf[i][2 * j]     += tt.x;
                    accf[i][2 * j + 1] += tt.y;
                    hacc[i][j] = __float2half2_rn(0.f);
                }
            }
        }
    }

    // store fp16 partial sums [ks][F][BL]
    const int lflat = l0 + (tid >> 4) * 4;
    __half* pout = g_part + (size_t)ks * (FF * BL);
#pragma unroll
    for (int i = 0; i < 4; i++) {
        __half2 h0 = __floats2half2_rn(accf[i][0], accf[i][1]);
        __half2 h1 = __floats2half2_rn(accf[i][2], accf[i][3]);
        uint2 st;
        st.x = *reinterpret_cast<uint32_t*>(&h0);
        st.y = *reinterpret_cast<uint32_t*>(&h1);
        int f = f0 + 4 * tc + i;
        *reinterpret_cast<uint2*>(&pout[(size_t)f * BL + lflat]) = st;
    }
}

// ---------------- reduce: out[b][f][l] = -4 * sum_ks part[ks][f][b*784+l] ----------------
// 8 outputs/thread, 16B loads per split. 784 blocks x 256 threads.
__global__ void __launch_bounds__(256) reduce_kernel(float* __restrict__ out) {
    int i = blockIdx.x * 256 + threadIdx.x;     // 8-output group index, < 200704
    int o = i * 8;
    int b = o / (FF * LL);
    int rem = o - b * (FF * LL);
    int f = rem / LL;
    int l = rem - f * LL;                        // 784 % 8 == 0 -> one (b,f) per group
    size_t p = (size_t)f * BL + b * LL + l;      // halves, 8-aligned

    float s[8] = {0.f, 0.f, 0.f, 0.f, 0.f, 0.f, 0.f, 0.f};
#pragma unroll
    for (int ks = 0; ks < KSPL; ks++) {
        uint4 u = *reinterpret_cast<const uint4*>(&g_part[(size_t)ks * (FF * BL) + p]);
        uint32_t uu[4] = {u.x, u.y, u.z, u.w};
#pragma unroll
        for (int j = 0; j < 4; j++) {
            float2 a = __half22float2(*reinterpret_cast<__half2*>(&uu[j]));
            s[2 * j]     += a.x;
            s[2 * j + 1] += a.y;
        }
    }
    float4* o4 = reinterpret_cast<float4*>(out + o);
    o4[0] = make_float4(-4.f * s[0], -4.f * s[1], -4.f * s[2], -4.f * s[3]);
    o4[1] = make_float4(-4.f * s[4], -4.f * s[5], -4.f * s[6], -4.f * s[7]);
}

extern "C" void kernel_launch(void* const* d_in, const int* in_sizes, int n_in,
                              void* d_out, int out_size) {
    const float* x  = (const float*)d_in[0];   // [16,128,28,28]
    const float* Wg = (const float*)d_in[1];   // [128,128,3,3]
    float* out = (float*)d_out;                // [16,128,28,28]

    prep_kernel<<<P_BLOCKS + W_BLOCKS, 256>>>(x, Wg);

    dim3 grid(NLT /*196*/, 2 * KSPL /*12*/, 1);
    adder_kernel<<<grid, 256>>>();

    reduce_kernel<<<(BB * FF * LL / 8) / 256 /*784*/, 256>>>(out);
}